// round 17
// baseline (speedup 1.0000x reference)
#include <cuda_runtime.h>
#include <cuda_fp16.h>
#include <cstdint>

// NSSTDecomposition via fp16 m16n8k16 mma.sync — COMBINED implicit GEMM.
// All 28 filters zero-extended into one 19(dy) x 20(dx-pad) window:
// D[pixels, 32 dirs] = A[pixels, K=384] x W^T, 24 k16-groups, N=32 (28 real).
// n: [0-3]=s0(11x11,+4 offset) [4-11]=s1(15x15,+2) [12-27]=s2(19x19) = channel order.
// A-loads amortize over NT=4 n-tiles (R14 ncu: crossbar 80% vs tensor 37%).

#define IMG_W   512
#define IMG_HW  (512*512)
#define WROWS   23             // 4 rows + dy up to 19 (K-pad overread) -> 3+19=22 max
#define WCOLS   152
#define WELEMS  (WROWS*WCOLS)  // 3496

#define NGRP    24             // K = 384 = 24 * 16
#define SLOTS   (NGRP*4)       // 96 B-fragment slots (4 n-tiles per group)

__device__ uint2 g_bfrag[3*SLOTS*32];

__device__ __forceinline__ void mma_f16(float* d,
    uint32_t a0, uint32_t a1, uint32_t a2, uint32_t a3, uint32_t b0, uint32_t b1) {
    asm volatile("mma.sync.aligned.m16n8k16.row.col.f32.f16.f16.f32 "
                 "{%0,%1,%2,%3}, {%4,%5,%6,%7}, {%8,%9}, {%0,%1,%2,%3};"
                 : "+f"(d[0]), "+f"(d[1]), "+f"(d[2]), "+f"(d[3])
                 : "r"(a0), "r"(a1), "r"(a2), "r"(a3), "r"(b0), "r"(b1));
}

// ---------------------------------------------------------------------------
// Weight of direction n at combined-window tap (dy, dx) on the 20-wide grid.
// ---------------------------------------------------------------------------
__device__ __forceinline__ float wval(
    int n, int dy, int dx, int c,
    const float* __restrict__ f0, const float* __restrict__ f1,
    const float* __restrict__ f2)
{
    if (dx >= 19 || dy >= 19 || n >= 28) return 0.0f;
    if (n < 4) {
        int ky = dy - 4, kx = dx - 4;
        if ((unsigned)ky < 11u && (unsigned)kx < 11u)
            return f0[(size_t)(c * 4 + n) * 121 + ky * 11 + kx];
        return 0.0f;
    } else if (n < 12) {
        int ky = dy - 2, kx = dx - 2;
        if ((unsigned)ky < 15u && (unsigned)kx < 15u)
            return f1[(size_t)(c * 8 + (n - 4)) * 225 + ky * 15 + kx];
        return 0.0f;
    }
    return f2[(size_t)(c * 16 + (n - 12)) * 361 + dy * 19 + dx];
}

// ---------------------------------------------------------------------------
// Prep: weights -> f16 fragment image. slot = g*4 + nt. Lane l: n = nt*8+(l>>2),
// kq=(l&3)*2 ; b0 = {W[n][k0],W[n][k0+1]}, b1 = {W[n][k0+8],W[n][k0+9]}.
// ---------------------------------------------------------------------------
__global__ void __launch_bounds__(256)
nsst_prep(const float* __restrict__ f0, const float* __restrict__ f1,
          const float* __restrict__ f2)
{
    int i = blockIdx.x * 256 + threadIdx.x;          // 3*96*32 = 9216
    if (i >= 3 * SLOTS * 32) return;
    int l    = i & 31;
    int slot = (i >> 5) % SLOTS;
    int c    = i / (SLOTS * 32);
    int g    = slot >> 2;
    int nt   = slot & 3;
    int n    = nt * 8 + (l >> 2);
    int kq   = (l & 3) * 2;

    uint32_t pk[2];
    #pragma unroll
    for (int r = 0; r < 2; r++) {
        int k  = g * 16 + kq + r * 8;
        int dy = k / 20, dx = k - dy * 20;
        float v0 = wval(n, dy, dx,     c, f0, f1, f2);
        float v1 = (dx + 1 < 20) ? wval(n, dy, dx + 1, c, f0, f1, f2) : 0.0f;
        __half2 hh = __halves2half2(__float2half_rn(v0), __float2half_rn(v1));
        pk[r] = *reinterpret_cast<uint32_t*>(&hh);
    }
    g_bfrag[i] = make_uint2(pk[0], pk[1]);
}

// ---------------------------------------------------------------------------
// Conv: grid (4 x-tiles, 128 y-quads, 12 bc), 256 threads = 8 warps.
// Warp w: y-row = w>>1, x-half = (w&1)*64; 4 m16-tiles x 4 n8-tiles, K=384.
// ---------------------------------------------------------------------------
__global__ void __launch_bounds__(256)
nsst_mma_conv(const float* __restrict__ img, float* __restrict__ out)
{
    __shared__ uint2 s_b[SLOTS * 32];                         // 24576 B
    __shared__ __align__(16) __half s_winA[WELEMS];           //  6992 B
    __shared__ __align__(16) __half s_winB[WELEMS];           //  6992 B (shift-1)

    const int tid = threadIdx.x;
    const int l   = tid & 31;
    const int w   = tid >> 5;
    const int x0  = blockIdx.x * 128;
    const int y0  = blockIdx.y * 4;
    const int bz  = blockIdx.z, b = bz / 3, c = bz % 3;

    // stage B fragments
    {
        const uint2* src = g_bfrag + (size_t)c * SLOTS * 32;
        for (int i = tid; i < SLOTS * 32; i += 256) s_b[i] = src[i];
    }
    // stage window (f16) + shifted copy, zero-padded
    {
        const float* src = img + (size_t)bz * IMG_HW;
        for (int i = tid; i < WELEMS; i += 256) {
            int iy = i / WCOLS, ix = i - iy * WCOLS;
            int gy = y0 + iy - 9, gx = x0 + ix - 9;
            float v = 0.0f;
            if ((unsigned)gy < 512u && (unsigned)gx < 512u) v = src[gy * IMG_W + gx];
            __half h = __float2half_rn(v);
            s_winA[i] = h;
            if (i > 0) s_winB[i - 1] = h;
        }
        if (tid == 0) s_winB[WELEMS - 1] = __float2half_rn(0.0f);
    }
    __syncthreads();

    const int row_w = w >> 1;
    const int xoff  = (w & 1) * 64;
    const int px    = l >> 2;
    const int kq    = (l & 3) * 2;
    const char* abase = ((l >> 2) & 1) ? ((const char*)s_winB - 2)
                                       : (const char*)s_winA;
    const int ebase = row_w * WCOLS + xoff + px;     // roff = 0 (RS = 9)

    float acc[4][4][4];
    #pragma unroll
    for (int mt = 0; mt < 4; mt++)
        #pragma unroll
        for (int nt = 0; nt < 4; nt++)
            #pragma unroll
            for (int q = 0; q < 4; q++) acc[mt][nt][q] = 0.0f;

    #pragma unroll
    for (int g = 0; g < NGRP; g++) {
        int k0 = g * 16 + kq;
        int k1 = k0 + 8;
        int dy0 = k0 / 20, dx0 = k0 - dy0 * 20;
        int dy1 = k1 / 20, dx1 = k1 - dy1 * 20;
        int e0 = ebase + dy0 * WCOLS + dx0;
        int e1 = ebase + dy1 * WCOLS + dx1;

        uint2 bf[4];
        #pragma unroll
        for (int nt = 0; nt < 4; nt++) bf[nt] = s_b[(g * 4 + nt) * 32 + l];

        #pragma unroll
        for (int mt = 0; mt < 4; mt++) {
            uint32_t a0 = *(const uint32_t*)(abase + (size_t)(e0 + mt * 16) * 2);
            uint32_t a1 = *(const uint32_t*)(abase + (size_t)(e0 + mt * 16 + 8) * 2);
            uint32_t a2 = *(const uint32_t*)(abase + (size_t)(e1 + mt * 16) * 2);
            uint32_t a3 = *(const uint32_t*)(abase + (size_t)(e1 + mt * 16 + 8) * 2);
            #pragma unroll
            for (int nt = 0; nt < 4; nt++)
                mma_f16(acc[mt][nt], a0, a1, a2, a3, bf[nt].x, bf[nt].y);
        }
    }

    // epilogue: channel = chbase + n (n-order == reference channel order)
    float* obase = out + (size_t)(b * 87 + c * 29) * IMG_HW
                       + (size_t)(y0 + row_w) * IMG_W;
    #pragma unroll
    for (int mt = 0; mt < 4; mt++) {
        int x = xoff + mt * 16 + px + x0;
        #pragma unroll
        for (int nt = 0; nt < 4; nt++) {
            int n = nt * 8 + kq;
            if (n < 28) {
                float* o = obase + (size_t)n * IMG_HW;
                o[x]              = acc[mt][nt][0];
                o[IMG_HW + x]     = acc[mt][nt][1];
                o[x + 8]          = acc[mt][nt][2];
                o[IMG_HW + x + 8] = acc[mt][nt][3];
            }
        }
    }
}

// ---------------------------------------------------------------------------
// Fused lowpass: 4x4 box mean + bilinear upsample (clamp == jax renorm edge).
// Block = 64x64 output region; 18x18 lowpass cells in smem. (verified R12/R13)
// ---------------------------------------------------------------------------
__global__ void __launch_bounds__(256)
nsst_lowpass(const float* __restrict__ img, float* __restrict__ out)
{
    __shared__ float s_cell[18 * 18];
    const int tid = threadIdx.x;
    const int x0 = blockIdx.x * 64;
    const int y0 = blockIdx.y * 64;
    const int bz = blockIdx.z, b = bz / 3, c = bz % 3;
    const int cyb = (y0 >> 2) - 1;
    const int cxb = (x0 >> 2) - 1;
    const float* src = img + (size_t)bz * IMG_HW;

    for (int i = tid; i < 324; i += 256) {
        int cy = min(127, max(0, cyb + i / 18));
        int cx = min(127, max(0, cxb + i % 18));
        const float* p = src + (size_t)(cy * 4) * IMG_W + cx * 4;
        float s = 0.0f;
        #pragma unroll
        for (int r = 0; r < 4; r++) {
            float4 v = *reinterpret_cast<const float4*>(p + r * IMG_W);
            s += v.x + v.y + v.z + v.w;
        }
        s_cell[i] = s * (1.0f / 16.0f);
    }
    __syncthreads();

    float* o = out + (size_t)(b * 87 + c * 29 + 28) * IMG_HW;
    #pragma unroll
    for (int j = 0; j < 16; j++) {
        int idx = tid + j * 256;                 // 0..4095
        int oy = y0 + (idx >> 6);
        int ox = x0 + (idx & 63);
        float sy = oy * 0.25f - 0.375f;          // (y+0.5)/4 - 0.5
        float sx = ox * 0.25f - 0.375f;
        int iy0 = (int)floorf(sy), ix0 = (int)floorf(sx);
        float fy = sy - (float)iy0, fx = sx - (float)ix0;
        int ly = iy0 - cyb, lx = ix0 - cxb;      // 0..16
        const float* cp = s_cell + ly * 18 + lx;
        float v00 = cp[0],  v01 = cp[1];
        float v10 = cp[18], v11 = cp[19];
        float top = v00 + fx * (v01 - v00);
        float bot = v10 + fx * (v11 - v10);
        o[(size_t)oy * IMG_W + ox] = top + fy * (bot - top);
    }
}

// ---------------------------------------------------------------------------
extern "C" void kernel_launch(void* const* d_in, const int* in_sizes, int n_in,
                              void* d_out, int out_size)
{
    const float* img = (const float*)d_in[0];
    const float* f0  = (const float*)d_in[1];
    const float* f1  = (const float*)d_in[2];
    const float* f2  = (const float*)d_in[3];
    float* out = (float*)d_out;

    nsst_prep<<<(3 * SLOTS * 32 + 255) / 256, 256>>>(f0, f1, f2);

    dim3 grid(4, 128, 12);
    nsst_mma_conv<<<grid, 256>>>(img, out);

    dim3 lgrid(8, 8, 12);
    nsst_lowpass<<<lgrid, 256>>>(img, out);
}